// round 13
// baseline (speedup 1.0000x reference)
#include <cuda_runtime.h>
#include <math.h>
#include <stdint.h>

#define NN 100000
#define EIN 1600000
#define ETOT (EIN + NN)

// ------------------------- scratch (static device globals) -------------------
__device__ float g_h1[NN * 128];    // layer1 linear out  [N,4,32]
__device__ float g_agg1[NN * 128];  // layer1 GAT out (normalized, biased, ELU)
__device__ float g_h2[NN * 64];     // layer2 linear out  [N,4,16]
__device__ float g_asrc1[NN * 4], g_adst1[NN * 4];
__device__ float g_asrc2[NN * 4], g_adst2[NN * 4];
__device__ int   g_deg[NN + 1];     // zero-init at load; scan re-zeroes each run
__device__ int   g_wptr[NN + 1];
__device__ int   g_rowptr[NN + 1];
__device__ int   g_esrc[ETOT];
__device__ float g_w1f[128 * 128];  // W1 in B-fragment order
__device__ float g_w2f[128 * 64];   // W2 in B-fragment order

// ------------------------- helpers -------------------------------------------
__device__ __forceinline__ float lrelu(float x) { return x > 0.f ? x : 0.2f * x; }

__device__ __forceinline__ uint32_t f2tf32(float x) {
    uint32_t r;
    asm("cvt.rna.tf32.f32 %0, %1;" : "=r"(r) : "f"(x));
    return r;
}

__device__ __forceinline__ void mma_tf32(float c[4], uint32_t a0, uint32_t a1,
                                         uint32_t a2, uint32_t a3,
                                         uint32_t b0, uint32_t b1) {
    asm volatile(
        "mma.sync.aligned.m16n8k8.row.col.f32.tf32.tf32.f32 "
        "{%0,%1,%2,%3}, {%4,%5,%6,%7}, {%8,%9}, {%0,%1,%2,%3};"
        : "+f"(c[0]), "+f"(c[1]), "+f"(c[2]), "+f"(c[3])
        : "r"(a0), "r"(a1), "r"(a2), "r"(a3), "r"(b0), "r"(b1));
}

// ------------------------- CSR build -----------------------------------------
__global__ void hist_kernel(const int* __restrict__ ei, int* __restrict__ deg) {
    int e2 = blockIdx.x * blockDim.x + threadIdx.x;
    if (e2 * 2 >= EIN) return;
    int2 d = *reinterpret_cast<const int2*>(ei + EIN + e2 * 2);
    atomicAdd(&deg[d.x], 1);
    atomicAdd(&deg[d.y], 1);
}

// reads deg, emits rowptr/wptr, and RE-ZEROES deg for the next invocation
__global__ void scan_kernel(int* __restrict__ deg, int* __restrict__ rowptr,
                            int* __restrict__ wptr) {
    __shared__ int psum[1024];
    const int t = threadIdx.x;
    const int CH = (NN + 1023) / 1024;
    const int base = t * CH;
    int sum = 0;
    for (int i = 0; i < CH; i++) {
        int idx = base + i;
        if (idx < NN) sum += deg[idx] + 1;  // +1 self loop
    }
    psum[t] = sum;
    __syncthreads();
    for (int off = 1; off < 1024; off <<= 1) {
        int v = (t >= off) ? psum[t - off] : 0;
        __syncthreads();
        psum[t] += v;
        __syncthreads();
    }
    int running = psum[t] - sum;
    for (int i = 0; i < CH; i++) {
        int idx = base + i;
        if (idx < NN) {
            int dv = deg[idx] + 1;
            deg[idx] = 0;               // reset for next run (replaces memset)
            rowptr[idx] = running;
            wptr[idx] = running;
            running += dv;
        }
    }
    if (t == 0) rowptr[NN] = ETOT;
}

__global__ void scatter_kernel(const int* __restrict__ ei, int* __restrict__ wptr,
                               int* __restrict__ esrc) {
    int e = blockIdx.x * blockDim.x + threadIdx.x;
    if (e >= ETOT) return;
    int s, d;
    if (e < EIN) { s = ei[e]; d = ei[EIN + e]; } else { s = d = e - EIN; }
    int pos = atomicAdd(&wptr[d], 1);
    esrc[pos] = s;
}

// --------------- both W reorders in ONE kernel -------------------------------
__global__ void reorderW_both(const float* __restrict__ W1, const float* __restrict__ W2,
                              float* __restrict__ W1f, float* __restrict__ W2f) {
    int gi = blockIdx.x * blockDim.x + threadIdx.x;
    const float* W;
    float* Wf;
    int i, NOUT;
    if (gi < 16 * 16 * 32) { W = W1; Wf = W1f; i = gi; NOUT = 128; }
    else if (gi < 16 * 16 * 32 + 16 * 8 * 32) { W = W2; Wf = W2f; i = gi - 16 * 16 * 32; NOUT = 64; }
    else return;
    int NT = NOUT / 8;
    int lane = i & 31;
    int nt = (i >> 5) % NT;
    int kk = (i >> 5) / NT;
    int krow = kk * 8 + (lane & 3);
    int ncol = nt * 8 + (lane >> 2);
    Wf[i * 2 + 0] = __uint_as_float(f2tf32(W[krow * NOUT + ncol]));
    Wf[i * 2 + 1] = __uint_as_float(f2tf32(W[(krow + 4) * NOUT + ncol]));
}

// --------- tf32 tensor-core GEMM + fused attention-coefficient epilogue ------
// K-chunked X staging (2 chunks of 64) -> xs is 32KB -> 2 CTAs/SM.
template <int NOUT>
__global__ void gemm_tc_kernel(const float* __restrict__ X, const float* __restrict__ Wf,
                               const float* __restrict__ ASRC, const float* __restrict__ ADST,
                               float* __restrict__ Y,
                               float* __restrict__ asrc, float* __restrict__ adst) {
    constexpr int NT = NOUT / 8;
    constexpr int NTH = NT / 4;
    extern __shared__ float smem[];
    float* xs = smem;               // 8192 floats (32KB)
    float* wf = smem + 8192;        // NOUT*128 floats

    const int tid = threadIdx.x;
    const int w = tid >> 5;
    const int lane = tid & 31;
    const int row0b = blockIdx.x * 128;

#pragma unroll 4
    for (int i = tid; i < NOUT * 128 / 4; i += 256)
        reinterpret_cast<float4*>(wf)[i] = reinterpret_cast<const float4*>(Wf)[i];

    float acc[NT][4];
#pragma unroll
    for (int nt = 0; nt < NT; nt++)
#pragma unroll
        for (int j = 0; j < 4; j++) acc[nt][j] = 0.f;

#pragma unroll
    for (int c = 0; c < 2; c++) {
        if (c > 0) __syncthreads();
#pragma unroll
        for (int it = 0; it < 8; it++) {
            int idx = tid + it * 256;
            int rl = idx >> 4;
            int j = idx & 15;
            int gr = row0b + rl;
            float4 v = (gr < NN)
                ? reinterpret_cast<const float4*>(X + (size_t)gr * 128)[c * 16 + j]
                : make_float4(0.f, 0.f, 0.f, 0.f);
            int ww = rl >> 4, r = rl & 15;
            int kk = j >> 1;
            int reg = ((j & 1) << 1) | (r >> 3);
            float* base = xs + (((ww * 8 + kk) * 32 + ((r & 7) << 2)) << 2) + reg;
            base[0]  = __uint_as_float(f2tf32(v.x));
            base[4]  = __uint_as_float(f2tf32(v.y));
            base[8]  = __uint_as_float(f2tf32(v.z));
            base[12] = __uint_as_float(f2tf32(v.w));
        }
        __syncthreads();
#pragma unroll
        for (int kk = 0; kk < 8; kk++) {
            float4 af = reinterpret_cast<const float4*>(xs)[(w * 8 + kk) * 32 + lane];
            uint32_t a0 = __float_as_uint(af.x), a1 = __float_as_uint(af.y);
            uint32_t a2 = __float_as_uint(af.z), a3 = __float_as_uint(af.w);
            const float2* bb = reinterpret_cast<const float2*>(wf)
                               + ((c * 8 + kk) * NT) * 32 + lane;
#pragma unroll
            for (int nt = 0; nt < NT; nt++) {
                float2 bf = bb[nt * 32];
                mma_tf32(acc[nt], a0, a1, a2, a3,
                         __float_as_uint(bf.x), __float_as_uint(bf.y));
            }
        }
    }

    int r0 = row0b + w * 16 + (lane >> 2);
    int r1 = r0 + 8;
    float ps0[4] = {0, 0, 0, 0}, pd0[4] = {0, 0, 0, 0};
    float ps1[4] = {0, 0, 0, 0}, pd1[4] = {0, 0, 0, 0};
#pragma unroll
    for (int nt = 0; nt < NT; nt++) {
        int col = nt * 8 + (lane & 3) * 2;
        float s0 = __ldg(ASRC + col), s1 = __ldg(ASRC + col + 1);
        float d0 = __ldg(ADST + col), d1 = __ldg(ADST + col + 1);
        int h = nt / NTH;
        ps0[h] += acc[nt][0] * s0 + acc[nt][1] * s1;
        pd0[h] += acc[nt][0] * d0 + acc[nt][1] * d1;
        ps1[h] += acc[nt][2] * s0 + acc[nt][3] * s1;
        pd1[h] += acc[nt][2] * d0 + acc[nt][3] * d1;
        if (r0 < NN)
            *reinterpret_cast<float2*>(&Y[(size_t)r0 * NOUT + col]) =
                make_float2(acc[nt][0], acc[nt][1]);
        if (r1 < NN)
            *reinterpret_cast<float2*>(&Y[(size_t)r1 * NOUT + col]) =
                make_float2(acc[nt][2], acc[nt][3]);
    }
#pragma unroll
    for (int off = 1; off <= 2; off <<= 1) {
#pragma unroll
        for (int h = 0; h < 4; h++) {
            ps0[h] += __shfl_xor_sync(0xffffffffu, ps0[h], off);
            pd0[h] += __shfl_xor_sync(0xffffffffu, pd0[h], off);
            ps1[h] += __shfl_xor_sync(0xffffffffu, ps1[h], off);
            pd1[h] += __shfl_xor_sync(0xffffffffu, pd1[h], off);
        }
    }
    if ((lane & 3) == 0) {
        if (r0 < NN)
#pragma unroll
            for (int h = 0; h < 4; h++) {
                asrc[r0 * 4 + h] = ps0[h];
                adst[r0 * 4 + h] = pd0[h];
            }
        if (r1 < NN)
#pragma unroll
            for (int h = 0; h < 4; h++) {
                asrc[r1 * 4 + h] = ps1[h];
                adst[r1 * 4 + h] = pd1[h];
            }
    }
}

// ---------- layer-1 gather: warp/node, 8x unroll, fused norm+bias+ELU --------
__global__ void gather1_kernel(const float* __restrict__ h, const float* __restrict__ asrc,
                               const float* __restrict__ adst,
                               const int* __restrict__ rowptr, const int* __restrict__ esrc,
                               const float* __restrict__ b1, float* __restrict__ out) {
    int node = (blockIdx.x * blockDim.x + threadIdx.x) >> 5;
    if (node >= NN) return;
    int lane = threadIdx.x & 31, head = lane >> 3;
    int rs = rowptr[node], re = rowptr[node + 1];
    float ad = adst[node * 4 + head];

    float4 acc = make_float4(0.f, 0.f, 0.f, 0.f);
    float den = 0.f;
    int e = rs;
    while (e + 8 <= re) {
        int s[8];
#pragma unroll
        for (int q = 0; q < 8; q++) s[q] = esrc[e + q];
        float4 hv[8];
#pragma unroll
        for (int q = 0; q < 8; q++)
            hv[q] = *reinterpret_cast<const float4*>(h + (size_t)s[q] * 128 + lane * 4);
        float wv[8];
#pragma unroll
        for (int q = 0; q < 8; q++)
            wv[q] = expf(lrelu(asrc[s[q] * 4 + head] + ad));
#pragma unroll
        for (int q = 0; q < 8; q++) {
            acc.x += wv[q] * hv[q].x;
            acc.y += wv[q] * hv[q].y;
            acc.z += wv[q] * hv[q].z;
            acc.w += wv[q] * hv[q].w;
            den += wv[q];
        }
        e += 8;
    }
    while (e + 4 <= re) {
        int s0 = esrc[e], s1 = esrc[e + 1], s2 = esrc[e + 2], s3 = esrc[e + 3];
        float4 h0 = *reinterpret_cast<const float4*>(h + (size_t)s0 * 128 + lane * 4);
        float4 h1 = *reinterpret_cast<const float4*>(h + (size_t)s1 * 128 + lane * 4);
        float4 h2 = *reinterpret_cast<const float4*>(h + (size_t)s2 * 128 + lane * 4);
        float4 h3 = *reinterpret_cast<const float4*>(h + (size_t)s3 * 128 + lane * 4);
        float w0 = expf(lrelu(asrc[s0 * 4 + head] + ad));
        float w1 = expf(lrelu(asrc[s1 * 4 + head] + ad));
        float w2 = expf(lrelu(asrc[s2 * 4 + head] + ad));
        float w3 = expf(lrelu(asrc[s3 * 4 + head] + ad));
        acc.x += w0 * h0.x + w1 * h1.x + w2 * h2.x + w3 * h3.x;
        acc.y += w0 * h0.y + w1 * h1.y + w2 * h2.y + w3 * h3.y;
        acc.z += w0 * h0.z + w1 * h1.z + w2 * h2.z + w3 * h3.z;
        acc.w += w0 * h0.w + w1 * h1.w + w2 * h2.w + w3 * h3.w;
        den += w0 + w1 + w2 + w3;
        e += 4;
    }
    while (e < re) {
        int s0 = esrc[e];
        float w0 = expf(lrelu(asrc[s0 * 4 + head] + ad));
        float4 h0 = *reinterpret_cast<const float4*>(h + (size_t)s0 * 128 + lane * 4);
        acc.x += w0 * h0.x; acc.y += w0 * h0.y;
        acc.z += w0 * h0.z; acc.w += w0 * h0.w;
        den += w0;
        e++;
    }
    float inv = 1.f / (den + 1e-16f);
    float4 b = reinterpret_cast<const float4*>(b1)[lane];
    float4 o;
    o.x = acc.x * inv + b.x; o.y = acc.y * inv + b.y;
    o.z = acc.z * inv + b.z; o.w = acc.w * inv + b.w;
    o.x = o.x > 0.f ? o.x : expm1f(o.x);
    o.y = o.y > 0.f ? o.y : expm1f(o.y);
    o.z = o.z > 0.f ? o.z : expm1f(o.z);
    o.w = o.w > 0.f ? o.w : expm1f(o.w);
    reinterpret_cast<float4*>(out + (size_t)node * 128)[lane] = o;
}

// ---- layer-2 gather: warp/node, 8x unroll, fused norm+bias+log_softmax -----
__global__ void gather2_kernel(const float* __restrict__ h, const float* __restrict__ asrc,
                               const float* __restrict__ adst,
                               const int* __restrict__ rowptr, const int* __restrict__ esrc,
                               const float* __restrict__ b2, float* __restrict__ out) {
    int node = (blockIdx.x * blockDim.x + threadIdx.x) >> 5;
    if (node >= NN) return;
    int lane = threadIdx.x & 31, head = lane >> 3;
    int rs = rowptr[node], re = rowptr[node + 1];
    float ad = adst[node * 4 + head];

    float2 acc = make_float2(0.f, 0.f);
    float den = 0.f;
    int e = rs;
    while (e + 8 <= re) {
        int s[8];
#pragma unroll
        for (int q = 0; q < 8; q++) s[q] = esrc[e + q];
        float2 hv[8];
#pragma unroll
        for (int q = 0; q < 8; q++)
            hv[q] = *reinterpret_cast<const float2*>(h + (size_t)s[q] * 64 + lane * 2);
        float wv[8];
#pragma unroll
        for (int q = 0; q < 8; q++)
            wv[q] = expf(lrelu(asrc[s[q] * 4 + head] + ad));
#pragma unroll
        for (int q = 0; q < 8; q++) {
            acc.x += wv[q] * hv[q].x;
            acc.y += wv[q] * hv[q].y;
            den += wv[q];
        }
        e += 8;
    }
    while (e + 4 <= re) {
        int s0 = esrc[e], s1 = esrc[e + 1], s2 = esrc[e + 2], s3 = esrc[e + 3];
        float2 h0 = *reinterpret_cast<const float2*>(h + (size_t)s0 * 64 + lane * 2);
        float2 h1 = *reinterpret_cast<const float2*>(h + (size_t)s1 * 64 + lane * 2);
        float2 h2 = *reinterpret_cast<const float2*>(h + (size_t)s2 * 64 + lane * 2);
        float2 h3 = *reinterpret_cast<const float2*>(h + (size_t)s3 * 64 + lane * 2);
        float w0 = expf(lrelu(asrc[s0 * 4 + head] + ad));
        float w1 = expf(lrelu(asrc[s1 * 4 + head] + ad));
        float w2 = expf(lrelu(asrc[s2 * 4 + head] + ad));
        float w3 = expf(lrelu(asrc[s3 * 4 + head] + ad));
        acc.x += w0 * h0.x + w1 * h1.x + w2 * h2.x + w3 * h3.x;
        acc.y += w0 * h0.y + w1 * h1.y + w2 * h2.y + w3 * h3.y;
        den += w0 + w1 + w2 + w3;
        e += 4;
    }
    while (e < re) {
        int s0 = esrc[e];
        float w0 = expf(lrelu(asrc[s0 * 4 + head] + ad));
        float2 h0 = *reinterpret_cast<const float2*>(h + (size_t)s0 * 64 + lane * 2);
        acc.x += w0 * h0.x; acc.y += w0 * h0.y;
        den += w0;
        e++;
    }
    float inv = 1.f / (den + 1e-16f);
    float2 b = reinterpret_cast<const float2*>(b2)[lane];
    float2 v;
    v.x = acc.x * inv + b.x;
    v.y = acc.y * inv + b.y;

    float mx = fmaxf(v.x, v.y);
#pragma unroll
    for (int off = 16; off >= 1; off >>= 1)
        mx = fmaxf(mx, __shfl_xor_sync(0xffffffffu, mx, off));
    float sm = expf(v.x - mx) + expf(v.y - mx);
#pragma unroll
    for (int off = 16; off >= 1; off >>= 1)
        sm += __shfl_xor_sync(0xffffffffu, sm, off);
    float ls = logf(sm);
    float2 o = make_float2(v.x - mx - ls, v.y - mx - ls);
    *reinterpret_cast<float2*>(out + (size_t)node * 64 + lane * 2) = o;
}

// ------------------------- launch --------------------------------------------
extern "C" void kernel_launch(void* const* d_in, const int* in_sizes, int n_in,
                              void* d_out, int out_size) {
    const float* x        = (const float*)d_in[0];
    const int*   ei       = (const int*)d_in[1];
    const float* W1       = (const float*)d_in[2];
    const float* att_src1 = (const float*)d_in[3];
    const float* att_dst1 = (const float*)d_in[4];
    const float* b1       = (const float*)d_in[5];
    const float* W2       = (const float*)d_in[6];
    const float* att_src2 = (const float*)d_in[7];
    const float* att_dst2 = (const float*)d_in[8];
    const float* b2       = (const float*)d_in[9];
    float* out = (float*)d_out;

    float *h1, *agg1, *h2, *asrc1, *adst1, *asrc2, *adst2, *w1f, *w2f;
    int *deg, *wptr, *rowptr, *esrc;
    cudaGetSymbolAddress((void**)&h1, g_h1);
    cudaGetSymbolAddress((void**)&agg1, g_agg1);
    cudaGetSymbolAddress((void**)&h2, g_h2);
    cudaGetSymbolAddress((void**)&asrc1, g_asrc1);
    cudaGetSymbolAddress((void**)&adst1, g_adst1);
    cudaGetSymbolAddress((void**)&asrc2, g_asrc2);
    cudaGetSymbolAddress((void**)&adst2, g_adst2);
    cudaGetSymbolAddress((void**)&deg, g_deg);
    cudaGetSymbolAddress((void**)&wptr, g_wptr);
    cudaGetSymbolAddress((void**)&rowptr, g_rowptr);
    cudaGetSymbolAddress((void**)&esrc, g_esrc);
    cudaGetSymbolAddress((void**)&w1f, g_w1f);
    cudaGetSymbolAddress((void**)&w2f, g_w2f);

    const int TB = 256;
    const int gemm_blocks = (NN + 127) / 128;
    const int node_warp_blocks = (NN * 32 + TB - 1) / TB;
    const int smem1 = (8192 + 128 * 128) * 4;   // 96KB -> 2 CTAs/SM
    const int smem2 = (8192 + 128 * 64) * 4;    // 64KB

    cudaFuncSetAttribute(gemm_tc_kernel<128>,
                         cudaFuncAttributeMaxDynamicSharedMemorySize, smem1);
    cudaFuncSetAttribute(gemm_tc_kernel<64>,
                         cudaFuncAttributeMaxDynamicSharedMemorySize, smem2);

    // ---- fork a side stream: CSR build runs concurrently with gemm1 --------
    cudaStream_t s2;
    cudaStreamCreateWithFlags(&s2, cudaStreamNonBlocking);
    cudaEvent_t evFork, evJoin;
    cudaEventCreateWithFlags(&evFork, cudaEventDisableTiming);
    cudaEventCreateWithFlags(&evJoin, cudaEventDisableTiming);

    cudaEventRecord(evFork, 0);
    cudaStreamWaitEvent(s2, evFork, 0);

    // side stream: CSR chain; deg is pre-zeroed (load init / previous scan)
    hist_kernel<<<(EIN / 2 + TB - 1) / TB, TB, 0, s2>>>(ei, deg);          // #1
    scan_kernel<<<1, 1024, 0, s2>>>(deg, rowptr, wptr);                    // #2
    scatter_kernel<<<(ETOT + TB - 1) / TB, TB, 0, s2>>>(ei, wptr, esrc);   // #3
    cudaEventRecord(evJoin, s2);

    // main stream: merged weight reorder + layer-1 GEMM
    reorderW_both<<<(16 * 24 * 32 + TB - 1) / TB, TB>>>(W1, W2, w1f, w2f); // #4
    gemm_tc_kernel<128><<<gemm_blocks, TB, smem1>>>(x, w1f, att_src1, att_dst1,
                                                    h1, asrc1, adst1);     // #5

    // join: gather1 needs both gemm1 outputs and the CSR
    cudaStreamWaitEvent(0, evJoin, 0);
    gather1_kernel<<<node_warp_blocks, TB>>>(h1, asrc1, adst1, rowptr, esrc,
                                             b1, agg1);                    // #6 <- ncu
    // ---- layer 2 ----
    gemm_tc_kernel<64><<<gemm_blocks, TB, smem2>>>(agg1, w2f, att_src2, att_dst2,
                                                   h2, asrc2, adst2);
    gather2_kernel<<<node_warp_blocks, TB>>>(h2, asrc2, adst2, rowptr, esrc, b2, out);
}

// round 14
// speedup vs baseline: 1.0068x; 1.0068x over previous
#include <cuda_runtime.h>
#include <math.h>
#include <stdint.h>

#define NN 100000
#define EIN 1600000
#define ETOT (EIN + NN)

// ------------------------- scratch (static device globals) -------------------
__device__ float g_h1[NN * 128];    // layer1 linear out  [N,4,32]
__device__ float g_agg1[NN * 128];  // layer1 GAT out (normalized, biased, ELU)
__device__ float g_h2[NN * 64];     // layer2 linear out  [N,4,16]
__device__ float g_asrc1[NN * 4], g_adst1[NN * 4];
__device__ float g_asrc2[NN * 4], g_adst2[NN * 4];
__device__ int   g_deg[NN + 1];     // zero-init at load; scan re-zeroes each run
__device__ int   g_wptr[NN + 1];
__device__ int   g_rowptr[NN + 1];
__device__ int   g_esrc[ETOT];
__device__ float g_w1f[128 * 128];  // W1 in B-fragment order
__device__ float g_w2f[128 * 64];   // W2 in B-fragment order

// ------------------------- helpers -------------------------------------------
__device__ __forceinline__ float lrelu(float x) { return x > 0.f ? x : 0.2f * x; }

__device__ __forceinline__ uint32_t f2tf32(float x) {
    uint32_t r;
    asm("cvt.rna.tf32.f32 %0, %1;" : "=r"(r) : "f"(x));
    return r;
}

__device__ __forceinline__ void mma_tf32(float c[4], uint32_t a0, uint32_t a1,
                                         uint32_t a2, uint32_t a3,
                                         uint32_t b0, uint32_t b1) {
    asm volatile(
        "mma.sync.aligned.m16n8k8.row.col.f32.tf32.tf32.f32 "
        "{%0,%1,%2,%3}, {%4,%5,%6,%7}, {%8,%9}, {%0,%1,%2,%3};"
        : "+f"(c[0]), "+f"(c[1]), "+f"(c[2]), "+f"(c[3])
        : "r"(a0), "r"(a1), "r"(a2), "r"(a3), "r"(b0), "r"(b1));
}

// ------------------------- CSR build -----------------------------------------
__global__ void hist_kernel(const int* __restrict__ ei, int* __restrict__ deg) {
    int e2 = blockIdx.x * blockDim.x + threadIdx.x;
    if (e2 * 2 >= EIN) return;
    int2 d = *reinterpret_cast<const int2*>(ei + EIN + e2 * 2);
    atomicAdd(&deg[d.x], 1);
    atomicAdd(&deg[d.y], 1);
}

// reads deg, emits rowptr/wptr, and RE-ZEROES deg for the next invocation
__global__ void scan_kernel(int* __restrict__ deg, int* __restrict__ rowptr,
                            int* __restrict__ wptr) {
    __shared__ int psum[1024];
    const int t = threadIdx.x;
    const int CH = (NN + 1023) / 1024;
    const int base = t * CH;
    int sum = 0;
    for (int i = 0; i < CH; i++) {
        int idx = base + i;
        if (idx < NN) sum += deg[idx] + 1;  // +1 self loop
    }
    psum[t] = sum;
    __syncthreads();
    for (int off = 1; off < 1024; off <<= 1) {
        int v = (t >= off) ? psum[t - off] : 0;
        __syncthreads();
        psum[t] += v;
        __syncthreads();
    }
    int running = psum[t] - sum;
    for (int i = 0; i < CH; i++) {
        int idx = base + i;
        if (idx < NN) {
            int dv = deg[idx] + 1;
            deg[idx] = 0;               // reset for next run (replaces memset)
            rowptr[idx] = running;
            wptr[idx] = running;
            running += dv;
        }
    }
    if (t == 0) rowptr[NN] = ETOT;
}

__global__ void scatter_kernel(const int* __restrict__ ei, int* __restrict__ wptr,
                               int* __restrict__ esrc) {
    int e = blockIdx.x * blockDim.x + threadIdx.x;
    if (e >= ETOT) return;
    int s, d;
    if (e < EIN) { s = ei[e]; d = ei[EIN + e]; } else { s = d = e - EIN; }
    int pos = atomicAdd(&wptr[d], 1);
    esrc[pos] = s;
}

// --------------- both W reorders in ONE kernel -------------------------------
__global__ void reorderW_both(const float* __restrict__ W1, const float* __restrict__ W2,
                              float* __restrict__ W1f, float* __restrict__ W2f) {
    int gi = blockIdx.x * blockDim.x + threadIdx.x;
    const float* W;
    float* Wf;
    int i, NOUT;
    if (gi < 16 * 16 * 32) { W = W1; Wf = W1f; i = gi; NOUT = 128; }
    else if (gi < 16 * 16 * 32 + 16 * 8 * 32) { W = W2; Wf = W2f; i = gi - 16 * 16 * 32; NOUT = 64; }
    else return;
    int NT = NOUT / 8;
    int lane = i & 31;
    int nt = (i >> 5) % NT;
    int kk = (i >> 5) / NT;
    int krow = kk * 8 + (lane & 3);
    int ncol = nt * 8 + (lane >> 2);
    Wf[i * 2 + 0] = __uint_as_float(f2tf32(W[krow * NOUT + ncol]));
    Wf[i * 2 + 1] = __uint_as_float(f2tf32(W[(krow + 4) * NOUT + ncol]));
}

// --------- tf32 tensor-core GEMM + fused attention-coefficient epilogue ------
// K-chunked X staging (2 chunks of 64) -> xs is 32KB -> 2 CTAs/SM.
template <int NOUT>
__global__ void gemm_tc_kernel(const float* __restrict__ X, const float* __restrict__ Wf,
                               const float* __restrict__ ASRC, const float* __restrict__ ADST,
                               float* __restrict__ Y,
                               float* __restrict__ asrc, float* __restrict__ adst) {
    constexpr int NT = NOUT / 8;
    constexpr int NTH = NT / 4;
    extern __shared__ float smem[];
    float* xs = smem;               // 8192 floats (32KB)
    float* wf = smem + 8192;        // NOUT*128 floats

    const int tid = threadIdx.x;
    const int w = tid >> 5;
    const int lane = tid & 31;
    const int row0b = blockIdx.x * 128;

#pragma unroll 4
    for (int i = tid; i < NOUT * 128 / 4; i += 256)
        reinterpret_cast<float4*>(wf)[i] = reinterpret_cast<const float4*>(Wf)[i];

    float acc[NT][4];
#pragma unroll
    for (int nt = 0; nt < NT; nt++)
#pragma unroll
        for (int j = 0; j < 4; j++) acc[nt][j] = 0.f;

#pragma unroll
    for (int c = 0; c < 2; c++) {
        if (c > 0) __syncthreads();
#pragma unroll
        for (int it = 0; it < 8; it++) {
            int idx = tid + it * 256;
            int rl = idx >> 4;
            int j = idx & 15;
            int gr = row0b + rl;
            float4 v = (gr < NN)
                ? reinterpret_cast<const float4*>(X + (size_t)gr * 128)[c * 16 + j]
                : make_float4(0.f, 0.f, 0.f, 0.f);
            int ww = rl >> 4, r = rl & 15;
            int kk = j >> 1;
            int reg = ((j & 1) << 1) | (r >> 3);
            float* base = xs + (((ww * 8 + kk) * 32 + ((r & 7) << 2)) << 2) + reg;
            base[0]  = __uint_as_float(f2tf32(v.x));
            base[4]  = __uint_as_float(f2tf32(v.y));
            base[8]  = __uint_as_float(f2tf32(v.z));
            base[12] = __uint_as_float(f2tf32(v.w));
        }
        __syncthreads();
#pragma unroll
        for (int kk = 0; kk < 8; kk++) {
            float4 af = reinterpret_cast<const float4*>(xs)[(w * 8 + kk) * 32 + lane];
            uint32_t a0 = __float_as_uint(af.x), a1 = __float_as_uint(af.y);
            uint32_t a2 = __float_as_uint(af.z), a3 = __float_as_uint(af.w);
            const float2* bb = reinterpret_cast<const float2*>(wf)
                               + ((c * 8 + kk) * NT) * 32 + lane;
#pragma unroll
            for (int nt = 0; nt < NT; nt++) {
                float2 bf = bb[nt * 32];
                mma_tf32(acc[nt], a0, a1, a2, a3,
                         __float_as_uint(bf.x), __float_as_uint(bf.y));
            }
        }
    }

    int r0 = row0b + w * 16 + (lane >> 2);
    int r1 = r0 + 8;
    float ps0[4] = {0, 0, 0, 0}, pd0[4] = {0, 0, 0, 0};
    float ps1[4] = {0, 0, 0, 0}, pd1[4] = {0, 0, 0, 0};
#pragma unroll
    for (int nt = 0; nt < NT; nt++) {
        int col = nt * 8 + (lane & 3) * 2;
        float s0 = __ldg(ASRC + col), s1 = __ldg(ASRC + col + 1);
        float d0 = __ldg(ADST + col), d1 = __ldg(ADST + col + 1);
        int h = nt / NTH;
        ps0[h] += acc[nt][0] * s0 + acc[nt][1] * s1;
        pd0[h] += acc[nt][0] * d0 + acc[nt][1] * d1;
        ps1[h] += acc[nt][2] * s0 + acc[nt][3] * s1;
        pd1[h] += acc[nt][2] * d0 + acc[nt][3] * d1;
        if (r0 < NN)
            *reinterpret_cast<float2*>(&Y[(size_t)r0 * NOUT + col]) =
                make_float2(acc[nt][0], acc[nt][1]);
        if (r1 < NN)
            *reinterpret_cast<float2*>(&Y[(size_t)r1 * NOUT + col]) =
                make_float2(acc[nt][2], acc[nt][3]);
    }
#pragma unroll
    for (int off = 1; off <= 2; off <<= 1) {
#pragma unroll
        for (int h = 0; h < 4; h++) {
            ps0[h] += __shfl_xor_sync(0xffffffffu, ps0[h], off);
            pd0[h] += __shfl_xor_sync(0xffffffffu, pd0[h], off);
            ps1[h] += __shfl_xor_sync(0xffffffffu, ps1[h], off);
            pd1[h] += __shfl_xor_sync(0xffffffffu, pd1[h], off);
        }
    }
    if ((lane & 3) == 0) {
        if (r0 < NN)
#pragma unroll
            for (int h = 0; h < 4; h++) {
                asrc[r0 * 4 + h] = ps0[h];
                adst[r0 * 4 + h] = pd0[h];
            }
        if (r1 < NN)
#pragma unroll
            for (int h = 0; h < 4; h++) {
                asrc[r1 * 4 + h] = ps1[h];
                adst[r1 * 4 + h] = pd1[h];
            }
    }
}

// ---------- layer-1 gather aggregation: warp/node, 4x unroll, fused epilogue -
__global__ void gather1_kernel(const float* __restrict__ h, const float* __restrict__ asrc,
                               const float* __restrict__ adst,
                               const int* __restrict__ rowptr, const int* __restrict__ esrc,
                               const float* __restrict__ b1, float* __restrict__ out) {
    int node = (blockIdx.x * blockDim.x + threadIdx.x) >> 5;
    if (node >= NN) return;
    int lane = threadIdx.x & 31, head = lane >> 3;
    int rs = rowptr[node], re = rowptr[node + 1];
    float ad = adst[node * 4 + head];

    float4 acc = make_float4(0.f, 0.f, 0.f, 0.f);
    float den = 0.f;
    int e = rs;
    while (e + 4 <= re) {
        int s0 = esrc[e], s1 = esrc[e + 1], s2 = esrc[e + 2], s3 = esrc[e + 3];
        float4 h0 = *reinterpret_cast<const float4*>(h + (size_t)s0 * 128 + lane * 4);
        float4 h1 = *reinterpret_cast<const float4*>(h + (size_t)s1 * 128 + lane * 4);
        float4 h2 = *reinterpret_cast<const float4*>(h + (size_t)s2 * 128 + lane * 4);
        float4 h3 = *reinterpret_cast<const float4*>(h + (size_t)s3 * 128 + lane * 4);
        float w0 = expf(lrelu(asrc[s0 * 4 + head] + ad));
        float w1 = expf(lrelu(asrc[s1 * 4 + head] + ad));
        float w2 = expf(lrelu(asrc[s2 * 4 + head] + ad));
        float w3 = expf(lrelu(asrc[s3 * 4 + head] + ad));
        acc.x += w0 * h0.x + w1 * h1.x + w2 * h2.x + w3 * h3.x;
        acc.y += w0 * h0.y + w1 * h1.y + w2 * h2.y + w3 * h3.y;
        acc.z += w0 * h0.z + w1 * h1.z + w2 * h2.z + w3 * h3.z;
        acc.w += w0 * h0.w + w1 * h1.w + w2 * h2.w + w3 * h3.w;
        den += w0 + w1 + w2 + w3;
        e += 4;
    }
    while (e < re) {
        int s0 = esrc[e];
        float w0 = expf(lrelu(asrc[s0 * 4 + head] + ad));
        float4 h0 = *reinterpret_cast<const float4*>(h + (size_t)s0 * 128 + lane * 4);
        acc.x += w0 * h0.x; acc.y += w0 * h0.y;
        acc.z += w0 * h0.z; acc.w += w0 * h0.w;
        den += w0;
        e++;
    }
    float inv = 1.f / (den + 1e-16f);
    float4 b = reinterpret_cast<const float4*>(b1)[lane];
    float4 o;
    o.x = acc.x * inv + b.x; o.y = acc.y * inv + b.y;
    o.z = acc.z * inv + b.z; o.w = acc.w * inv + b.w;
    o.x = o.x > 0.f ? o.x : expm1f(o.x);
    o.y = o.y > 0.f ? o.y : expm1f(o.y);
    o.z = o.z > 0.f ? o.z : expm1f(o.z);
    o.w = o.w > 0.f ? o.w : expm1f(o.w);
    reinterpret_cast<float4*>(out + (size_t)node * 128)[lane] = o;
}

// ---- layer-2 gather: warp/node, 4x unroll, fused norm+bias+log_softmax -----
__global__ void gather2_kernel(const float* __restrict__ h, const float* __restrict__ asrc,
                               const float* __restrict__ adst,
                               const int* __restrict__ rowptr, const int* __restrict__ esrc,
                               const float* __restrict__ b2, float* __restrict__ out) {
    int node = (blockIdx.x * blockDim.x + threadIdx.x) >> 5;
    if (node >= NN) return;
    int lane = threadIdx.x & 31, head = lane >> 3;
    int rs = rowptr[node], re = rowptr[node + 1];
    float ad = adst[node * 4 + head];

    float2 acc = make_float2(0.f, 0.f);
    float den = 0.f;
    int e = rs;
    while (e + 4 <= re) {
        int s0 = esrc[e], s1 = esrc[e + 1], s2 = esrc[e + 2], s3 = esrc[e + 3];
        float2 h0 = *reinterpret_cast<const float2*>(h + (size_t)s0 * 64 + lane * 2);
        float2 h1 = *reinterpret_cast<const float2*>(h + (size_t)s1 * 64 + lane * 2);
        float2 h2 = *reinterpret_cast<const float2*>(h + (size_t)s2 * 64 + lane * 2);
        float2 h3 = *reinterpret_cast<const float2*>(h + (size_t)s3 * 64 + lane * 2);
        float w0 = expf(lrelu(asrc[s0 * 4 + head] + ad));
        float w1 = expf(lrelu(asrc[s1 * 4 + head] + ad));
        float w2 = expf(lrelu(asrc[s2 * 4 + head] + ad));
        float w3 = expf(lrelu(asrc[s3 * 4 + head] + ad));
        acc.x += w0 * h0.x + w1 * h1.x + w2 * h2.x + w3 * h3.x;
        acc.y += w0 * h0.y + w1 * h1.y + w2 * h2.y + w3 * h3.y;
        den += w0 + w1 + w2 + w3;
        e += 4;
    }
    while (e < re) {
        int s0 = esrc[e];
        float w0 = expf(lrelu(asrc[s0 * 4 + head] + ad));
        float2 h0 = *reinterpret_cast<const float2*>(h + (size_t)s0 * 64 + lane * 2);
        acc.x += w0 * h0.x; acc.y += w0 * h0.y;
        den += w0;
        e++;
    }
    float inv = 1.f / (den + 1e-16f);
    float2 b = reinterpret_cast<const float2*>(b2)[lane];
    float2 v;
    v.x = acc.x * inv + b.x;
    v.y = acc.y * inv + b.y;

    float mx = fmaxf(v.x, v.y);
#pragma unroll
    for (int off = 16; off >= 1; off >>= 1)
        mx = fmaxf(mx, __shfl_xor_sync(0xffffffffu, mx, off));
    float sm = expf(v.x - mx) + expf(v.y - mx);
#pragma unroll
    for (int off = 16; off >= 1; off >>= 1)
        sm += __shfl_xor_sync(0xffffffffu, sm, off);
    float ls = logf(sm);
    float2 o = make_float2(v.x - mx - ls, v.y - mx - ls);
    *reinterpret_cast<float2*>(out + (size_t)node * 64 + lane * 2) = o;
}

// ------------------------- launch --------------------------------------------
extern "C" void kernel_launch(void* const* d_in, const int* in_sizes, int n_in,
                              void* d_out, int out_size) {
    const float* x        = (const float*)d_in[0];
    const int*   ei       = (const int*)d_in[1];
    const float* W1       = (const float*)d_in[2];
    const float* att_src1 = (const float*)d_in[3];
    const float* att_dst1 = (const float*)d_in[4];
    const float* b1       = (const float*)d_in[5];
    const float* W2       = (const float*)d_in[6];
    const float* att_src2 = (const float*)d_in[7];
    const float* att_dst2 = (const float*)d_in[8];
    const float* b2       = (const float*)d_in[9];
    float* out = (float*)d_out;

    float *h1, *agg1, *h2, *asrc1, *adst1, *asrc2, *adst2, *w1f, *w2f;
    int *deg, *wptr, *rowptr, *esrc;
    cudaGetSymbolAddress((void**)&h1, g_h1);
    cudaGetSymbolAddress((void**)&agg1, g_agg1);
    cudaGetSymbolAddress((void**)&h2, g_h2);
    cudaGetSymbolAddress((void**)&asrc1, g_asrc1);
    cudaGetSymbolAddress((void**)&adst1, g_adst1);
    cudaGetSymbolAddress((void**)&asrc2, g_asrc2);
    cudaGetSymbolAddress((void**)&adst2, g_adst2);
    cudaGetSymbolAddress((void**)&deg, g_deg);
    cudaGetSymbolAddress((void**)&wptr, g_wptr);
    cudaGetSymbolAddress((void**)&rowptr, g_rowptr);
    cudaGetSymbolAddress((void**)&esrc, g_esrc);
    cudaGetSymbolAddress((void**)&w1f, g_w1f);
    cudaGetSymbolAddress((void**)&w2f, g_w2f);

    const int TB = 256;
    const int gemm_blocks = (NN + 127) / 128;
    const int node_warp_blocks = (NN * 32 + TB - 1) / TB;
    const int smem1 = (8192 + 128 * 128) * 4;   // 96KB -> 2 CTAs/SM
    const int smem2 = (8192 + 128 * 64) * 4;    // 64KB

    cudaFuncSetAttribute(gemm_tc_kernel<128>,
                         cudaFuncAttributeMaxDynamicSharedMemorySize, smem1);
    cudaFuncSetAttribute(gemm_tc_kernel<64>,
                         cudaFuncAttributeMaxDynamicSharedMemorySize, smem2);

    // ---- fork a side stream: CSR build runs concurrently with gemm1 --------
    cudaStream_t s2;
    cudaStreamCreateWithFlags(&s2, cudaStreamNonBlocking);
    cudaEvent_t evFork, evJoin;
    cudaEventCreateWithFlags(&evFork, cudaEventDisableTiming);
    cudaEventCreateWithFlags(&evJoin, cudaEventDisableTiming);

    cudaEventRecord(evFork, 0);
    cudaStreamWaitEvent(s2, evFork, 0);

    // side stream: CSR chain; deg is pre-zeroed (load init / previous scan)
    hist_kernel<<<(EIN / 2 + TB - 1) / TB, TB, 0, s2>>>(ei, deg);
    scan_kernel<<<1, 1024, 0, s2>>>(deg, rowptr, wptr);
    scatter_kernel<<<(ETOT + TB - 1) / TB, TB, 0, s2>>>(ei, wptr, esrc);
    cudaEventRecord(evJoin, s2);

    // main stream: merged weight reorder + layer-1 GEMM
    reorderW_both<<<(16 * 24 * 32 + TB - 1) / TB, TB>>>(W1, W2, w1f, w2f);
    gemm_tc_kernel<128><<<gemm_blocks, TB, smem1>>>(x, w1f, att_src1, att_dst1,
                                                    h1, asrc1, adst1);

    // join: gather1 needs both gemm1 outputs and the CSR
    cudaStreamWaitEvent(0, evJoin, 0);
    gather1_kernel<<<node_warp_blocks, TB>>>(h1, asrc1, adst1, rowptr, esrc, b1, agg1);

    // ---- layer 2 ----
    gemm_tc_kernel<64><<<gemm_blocks, TB, smem2>>>(agg1, w2f, att_src2, att_dst2,
                                                   h2, asrc2, adst2);
    gather2_kernel<<<node_warp_blocks, TB>>>(h2, asrc2, adst2, rowptr, esrc, b2, out);
}

// round 15
// speedup vs baseline: 1.5413x; 1.5310x over previous
#include <cuda_runtime.h>
#include <math.h>
#include <stdint.h>

#define NN 100000
#define EIN 1600000
#define ETOT (EIN + NN)

// ------------------------- scratch (static device globals) -------------------
__device__ float g_h1[NN * 128];    // layer1 linear out  [N,4,32]
__device__ float g_agg1[NN * 128];  // layer1 GAT out (normalized, biased, ELU)
__device__ float g_h2[NN * 64];     // layer2 linear out  [N,4,16]
__device__ float g_asrc1[NN * 4], g_adst1[NN * 4];
__device__ float g_asrc2[NN * 4], g_adst2[NN * 4];
__device__ int   g_deg[NN + 1];
__device__ int   g_wptr[NN + 1];
__device__ int   g_rowptr[NN + 1];
__device__ int   g_esrc[ETOT];
__device__ float g_w1f[128 * 128];  // W1 in B-fragment order
__device__ float g_w2f[128 * 64];   // W2 in B-fragment order

// ------------------------- helpers -------------------------------------------
__device__ __forceinline__ float lrelu(float x) { return x > 0.f ? x : 0.2f * x; }

__device__ __forceinline__ uint32_t f2tf32(float x) {
    uint32_t r;
    asm("cvt.rna.tf32.f32 %0, %1;" : "=r"(r) : "f"(x));
    return r;
}

__device__ __forceinline__ void mma_tf32(float c[4], uint32_t a0, uint32_t a1,
                                         uint32_t a2, uint32_t a3,
                                         uint32_t b0, uint32_t b1) {
    asm volatile(
        "mma.sync.aligned.m16n8k8.row.col.f32.tf32.tf32.f32 "
        "{%0,%1,%2,%3}, {%4,%5,%6,%7}, {%8,%9}, {%0,%1,%2,%3};"
        : "+f"(c[0]), "+f"(c[1]), "+f"(c[2]), "+f"(c[3])
        : "r"(a0), "r"(a1), "r"(a2), "r"(a3), "r"(b0), "r"(b1));
}

// ------------------------- CSR build -----------------------------------------
__global__ void hist_kernel(const int* __restrict__ ei, int* __restrict__ deg) {
    int e2 = blockIdx.x * blockDim.x + threadIdx.x;
    if (e2 * 2 >= EIN) return;
    int2 d = *reinterpret_cast<const int2*>(ei + EIN + e2 * 2);
    atomicAdd(&deg[d.x], 1);
    atomicAdd(&deg[d.y], 1);
}

__global__ void scan_kernel(const int* __restrict__ deg, int* __restrict__ rowptr,
                            int* __restrict__ wptr) {
    __shared__ int psum[1024];
    const int t = threadIdx.x;
    const int CH = (NN + 1023) / 1024;
    const int base = t * CH;
    int sum = 0;
    for (int i = 0; i < CH; i++) {
        int idx = base + i;
        if (idx < NN) sum += deg[idx] + 1;  // +1 self loop
    }
    psum[t] = sum;
    __syncthreads();
    for (int off = 1; off < 1024; off <<= 1) {
        int v = (t >= off) ? psum[t - off] : 0;
        __syncthreads();
        psum[t] += v;
        __syncthreads();
    }
    int running = psum[t] - sum;
    for (int i = 0; i < CH; i++) {
        int idx = base + i;
        if (idx < NN) {
            int dv = deg[idx] + 1;
            rowptr[idx] = running;
            wptr[idx] = running;
            running += dv;
        }
    }
    if (t == 0) rowptr[NN] = ETOT;
}

__global__ void scatter_kernel(const int* __restrict__ ei, int* __restrict__ wptr,
                               int* __restrict__ esrc) {
    int e = blockIdx.x * blockDim.x + threadIdx.x;
    if (e >= ETOT) return;
    int s, d;
    if (e < EIN) { s = ei[e]; d = ei[EIN + e]; } else { s = d = e - EIN; }
    int pos = atomicAdd(&wptr[d], 1);
    esrc[pos] = s;
}

// --------------- W reorder into mma B-fragment order (standalone) ------------
__global__ void reorderW_kernel(const float* __restrict__ W, float* __restrict__ Wf,
                                int NOUT) {
    int NT = NOUT / 8;
    int i = blockIdx.x * blockDim.x + threadIdx.x;
    if (i >= 16 * NT * 32) return;
    int lane = i & 31;
    int nt = (i >> 5) % NT;
    int kk = (i >> 5) / NT;
    int krow = kk * 8 + (lane & 3);
    int ncol = nt * 8 + (lane >> 2);
    Wf[i * 2 + 0] = __uint_as_float(f2tf32(W[krow * NOUT + ncol]));
    Wf[i * 2 + 1] = __uint_as_float(f2tf32(W[(krow + 4) * NOUT + ncol]));
}

// --------- tf32 tensor-core GEMM + fused attention-coefficient epilogue ------
// K-chunked X staging (2 chunks of 64) -> xs is 32KB -> 2 CTAs/SM.
template <int NOUT>
__global__ void gemm_tc_kernel(const float* __restrict__ X, const float* __restrict__ Wf,
                               const float* __restrict__ ASRC, const float* __restrict__ ADST,
                               float* __restrict__ Y,
                               float* __restrict__ asrc, float* __restrict__ adst) {
    constexpr int NT = NOUT / 8;
    constexpr int NTH = NT / 4;
    extern __shared__ float smem[];
    float* xs = smem;               // 8 warps * 8 kk * 32 lanes * 4 = 8192 floats (32KB)
    float* wf = smem + 8192;        // NOUT*128 floats

    const int tid = threadIdx.x;
    const int w = tid >> 5;
    const int lane = tid & 31;
    const int row0b = blockIdx.x * 128;

    // stage W fragments (linear, coalesced)
#pragma unroll 4
    for (int i = tid; i < NOUT * 128 / 4; i += 256)
        reinterpret_cast<float4*>(wf)[i] = reinterpret_cast<const float4*>(Wf)[i];

    float acc[NT][4];
#pragma unroll
    for (int nt = 0; nt < NT; nt++)
#pragma unroll
        for (int j = 0; j < 4; j++) acc[nt][j] = 0.f;

#pragma unroll
    for (int c = 0; c < 2; c++) {
        if (c > 0) __syncthreads();  // all warps done with previous chunk
        // stage X chunk c into A-fragment order (+ tf32 rounding): 128 rows x 16 float4
#pragma unroll
        for (int it = 0; it < 8; it++) {
            int idx = tid + it * 256;
            int rl = idx >> 4;       // row in block (0..127)
            int j = idx & 15;        // float4 within chunk row
            int gr = row0b + rl;
            float4 v = (gr < NN)
                ? reinterpret_cast<const float4*>(X + (size_t)gr * 128)[c * 16 + j]
                : make_float4(0.f, 0.f, 0.f, 0.f);
            int ww = rl >> 4, r = rl & 15;
            int kk = j >> 1;         // local kk 0..7
            int reg = ((j & 1) << 1) | (r >> 3);
            float* base = xs + (((ww * 8 + kk) * 32 + ((r & 7) << 2)) << 2) + reg;
            base[0]  = __uint_as_float(f2tf32(v.x));
            base[4]  = __uint_as_float(f2tf32(v.y));
            base[8]  = __uint_as_float(f2tf32(v.z));
            base[12] = __uint_as_float(f2tf32(v.w));
        }
        __syncthreads();
#pragma unroll
        for (int kk = 0; kk < 8; kk++) {
            float4 af = reinterpret_cast<const float4*>(xs)[(w * 8 + kk) * 32 + lane];
            uint32_t a0 = __float_as_uint(af.x), a1 = __float_as_uint(af.y);
            uint32_t a2 = __float_as_uint(af.z), a3 = __float_as_uint(af.w);
            const float2* bb = reinterpret_cast<const float2*>(wf)
                               + ((c * 8 + kk) * NT) * 32 + lane;
#pragma unroll
            for (int nt = 0; nt < NT; nt++) {
                float2 bf = bb[nt * 32];
                mma_tf32(acc[nt], a0, a1, a2, a3,
                         __float_as_uint(bf.x), __float_as_uint(bf.y));
            }
        }
    }

    // epilogue: Y rows + per-head attention dots
    int r0 = row0b + w * 16 + (lane >> 2);
    int r1 = r0 + 8;
    float ps0[4] = {0, 0, 0, 0}, pd0[4] = {0, 0, 0, 0};
    float ps1[4] = {0, 0, 0, 0}, pd1[4] = {0, 0, 0, 0};
#pragma unroll
    for (int nt = 0; nt < NT; nt++) {
        int col = nt * 8 + (lane & 3) * 2;
        float s0 = __ldg(ASRC + col), s1 = __ldg(ASRC + col + 1);
        float d0 = __ldg(ADST + col), d1 = __ldg(ADST + col + 1);
        int h = nt / NTH;
        ps0[h] += acc[nt][0] * s0 + acc[nt][1] * s1;
        pd0[h] += acc[nt][0] * d0 + acc[nt][1] * d1;
        ps1[h] += acc[nt][2] * s0 + acc[nt][3] * s1;
        pd1[h] += acc[nt][2] * d0 + acc[nt][3] * d1;
        if (r0 < NN)
            *reinterpret_cast<float2*>(&Y[(size_t)r0 * NOUT + col]) =
                make_float2(acc[nt][0], acc[nt][1]);
        if (r1 < NN)
            *reinterpret_cast<float2*>(&Y[(size_t)r1 * NOUT + col]) =
                make_float2(acc[nt][2], acc[nt][3]);
    }
#pragma unroll
    for (int off = 1; off <= 2; off <<= 1) {
#pragma unroll
        for (int h = 0; h < 4; h++) {
            ps0[h] += __shfl_xor_sync(0xffffffffu, ps0[h], off);
            pd0[h] += __shfl_xor_sync(0xffffffffu, pd0[h], off);
            ps1[h] += __shfl_xor_sync(0xffffffffu, ps1[h], off);
            pd1[h] += __shfl_xor_sync(0xffffffffu, pd1[h], off);
        }
    }
    if ((lane & 3) == 0) {
        if (r0 < NN)
#pragma unroll
            for (int h = 0; h < 4; h++) {
                asrc[r0 * 4 + h] = ps0[h];
                adst[r0 * 4 + h] = pd0[h];
            }
        if (r1 < NN)
#pragma unroll
            for (int h = 0; h < 4; h++) {
                asrc[r1 * 4 + h] = ps1[h];
                adst[r1 * 4 + h] = pd1[h];
            }
    }
}

// ---------- layer-1 gather aggregation: warp/node, 4x unroll, fused epilogue -
__global__ void gather1_kernel(const float* __restrict__ h, const float* __restrict__ asrc,
                               const float* __restrict__ adst,
                               const int* __restrict__ rowptr, const int* __restrict__ esrc,
                               const float* __restrict__ b1, float* __restrict__ out) {
    int node = (blockIdx.x * blockDim.x + threadIdx.x) >> 5;
    if (node >= NN) return;
    int lane = threadIdx.x & 31, head = lane >> 3;
    int rs = rowptr[node], re = rowptr[node + 1];
    float ad = adst[node * 4 + head];

    float4 acc = make_float4(0.f, 0.f, 0.f, 0.f);
    float den = 0.f;
    int e = rs;
    while (e + 4 <= re) {
        int s0 = esrc[e], s1 = esrc[e + 1], s2 = esrc[e + 2], s3 = esrc[e + 3];
        float4 h0 = *reinterpret_cast<const float4*>(h + (size_t)s0 * 128 + lane * 4);
        float4 h1 = *reinterpret_cast<const float4*>(h + (size_t)s1 * 128 + lane * 4);
        float4 h2 = *reinterpret_cast<const float4*>(h + (size_t)s2 * 128 + lane * 4);
        float4 h3 = *reinterpret_cast<const float4*>(h + (size_t)s3 * 128 + lane * 4);
        float w0 = expf(lrelu(asrc[s0 * 4 + head] + ad));
        float w1 = expf(lrelu(asrc[s1 * 4 + head] + ad));
        float w2 = expf(lrelu(asrc[s2 * 4 + head] + ad));
        float w3 = expf(lrelu(asrc[s3 * 4 + head] + ad));
        acc.x += w0 * h0.x + w1 * h1.x + w2 * h2.x + w3 * h3.x;
        acc.y += w0 * h0.y + w1 * h1.y + w2 * h2.y + w3 * h3.y;
        acc.z += w0 * h0.z + w1 * h1.z + w2 * h2.z + w3 * h3.z;
        acc.w += w0 * h0.w + w1 * h1.w + w2 * h2.w + w3 * h3.w;
        den += w0 + w1 + w2 + w3;
        e += 4;
    }
    while (e < re) {
        int s0 = esrc[e];
        float w0 = expf(lrelu(asrc[s0 * 4 + head] + ad));
        float4 h0 = *reinterpret_cast<const float4*>(h + (size_t)s0 * 128 + lane * 4);
        acc.x += w0 * h0.x; acc.y += w0 * h0.y;
        acc.z += w0 * h0.z; acc.w += w0 * h0.w;
        den += w0;
        e++;
    }
    float inv = 1.f / (den + 1e-16f);
    float4 b = reinterpret_cast<const float4*>(b1)[lane];
    float4 o;
    o.x = acc.x * inv + b.x; o.y = acc.y * inv + b.y;
    o.z = acc.z * inv + b.z; o.w = acc.w * inv + b.w;
    o.x = o.x > 0.f ? o.x : expm1f(o.x);
    o.y = o.y > 0.f ? o.y : expm1f(o.y);
    o.z = o.z > 0.f ? o.z : expm1f(o.z);
    o.w = o.w > 0.f ? o.w : expm1f(o.w);
    reinterpret_cast<float4*>(out + (size_t)node * 128)[lane] = o;
}

// ---- layer-2 gather: warp/node, 4x unroll, fused norm+bias+log_softmax -----
__global__ void gather2_kernel(const float* __restrict__ h, const float* __restrict__ asrc,
                               const float* __restrict__ adst,
                               const int* __restrict__ rowptr, const int* __restrict__ esrc,
                               const float* __restrict__ b2, float* __restrict__ out) {
    int node = (blockIdx.x * blockDim.x + threadIdx.x) >> 5;
    if (node >= NN) return;
    int lane = threadIdx.x & 31, head = lane >> 3;
    int rs = rowptr[node], re = rowptr[node + 1];
    float ad = adst[node * 4 + head];

    float2 acc = make_float2(0.f, 0.f);
    float den = 0.f;
    int e = rs;
    while (e + 4 <= re) {
        int s0 = esrc[e], s1 = esrc[e + 1], s2 = esrc[e + 2], s3 = esrc[e + 3];
        float2 h0 = *reinterpret_cast<const float2*>(h + (size_t)s0 * 64 + lane * 2);
        float2 h1 = *reinterpret_cast<const float2*>(h + (size_t)s1 * 64 + lane * 2);
        float2 h2 = *reinterpret_cast<const float2*>(h + (size_t)s2 * 64 + lane * 2);
        float2 h3 = *reinterpret_cast<const float2*>(h + (size_t)s3 * 64 + lane * 2);
        float w0 = expf(lrelu(asrc[s0 * 4 + head] + ad));
        float w1 = expf(lrelu(asrc[s1 * 4 + head] + ad));
        float w2 = expf(lrelu(asrc[s2 * 4 + head] + ad));
        float w3 = expf(lrelu(asrc[s3 * 4 + head] + ad));
        acc.x += w0 * h0.x + w1 * h1.x + w2 * h2.x + w3 * h3.x;
        acc.y += w0 * h0.y + w1 * h1.y + w2 * h2.y + w3 * h3.y;
        den += w0 + w1 + w2 + w3;
        e += 4;
    }
    while (e < re) {
        int s0 = esrc[e];
        float w0 = expf(lrelu(asrc[s0 * 4 + head] + ad));
        float2 h0 = *reinterpret_cast<const float2*>(h + (size_t)s0 * 64 + lane * 2);
        acc.x += w0 * h0.x; acc.y += w0 * h0.y;
        den += w0;
        e++;
    }
    float inv = 1.f / (den + 1e-16f);
    float2 b = reinterpret_cast<const float2*>(b2)[lane];
    float2 v;
    v.x = acc.x * inv + b.x;
    v.y = acc.y * inv + b.y;

    float mx = fmaxf(v.x, v.y);
#pragma unroll
    for (int off = 16; off >= 1; off >>= 1)
        mx = fmaxf(mx, __shfl_xor_sync(0xffffffffu, mx, off));
    float sm = expf(v.x - mx) + expf(v.y - mx);
#pragma unroll
    for (int off = 16; off >= 1; off >>= 1)
        sm += __shfl_xor_sync(0xffffffffu, sm, off);
    float ls = logf(sm);
    float2 o = make_float2(v.x - mx - ls, v.y - mx - ls);
    *reinterpret_cast<float2*>(out + (size_t)node * 64 + lane * 2) = o;
}

// ------------------------- launch --------------------------------------------
extern "C" void kernel_launch(void* const* d_in, const int* in_sizes, int n_in,
                              void* d_out, int out_size) {
    const float* x        = (const float*)d_in[0];
    const int*   ei       = (const int*)d_in[1];
    const float* W1       = (const float*)d_in[2];
    const float* att_src1 = (const float*)d_in[3];
    const float* att_dst1 = (const float*)d_in[4];
    const float* b1       = (const float*)d_in[5];
    const float* W2       = (const float*)d_in[6];
    const float* att_src2 = (const float*)d_in[7];
    const float* att_dst2 = (const float*)d_in[8];
    const float* b2       = (const float*)d_in[9];
    float* out = (float*)d_out;

    float *h1, *agg1, *h2, *asrc1, *adst1, *asrc2, *adst2, *w1f, *w2f;
    int *deg, *wptr, *rowptr, *esrc;
    cudaGetSymbolAddress((void**)&h1, g_h1);
    cudaGetSymbolAddress((void**)&agg1, g_agg1);
    cudaGetSymbolAddress((void**)&h2, g_h2);
    cudaGetSymbolAddress((void**)&asrc1, g_asrc1);
    cudaGetSymbolAddress((void**)&adst1, g_adst1);
    cudaGetSymbolAddress((void**)&asrc2, g_asrc2);
    cudaGetSymbolAddress((void**)&adst2, g_adst2);
    cudaGetSymbolAddress((void**)&deg, g_deg);
    cudaGetSymbolAddress((void**)&wptr, g_wptr);
    cudaGetSymbolAddress((void**)&rowptr, g_rowptr);
    cudaGetSymbolAddress((void**)&esrc, g_esrc);
    cudaGetSymbolAddress((void**)&w1f, g_w1f);
    cudaGetSymbolAddress((void**)&w2f, g_w2f);

    const int TB = 256;
    const int gemm_blocks = (NN + 127) / 128;
    const int node_warp_blocks = (NN * 32 + TB - 1) / TB;
    const int smem1 = (8192 + 128 * 128) * 4;   // 96KB -> 2 CTAs/SM
    const int smem2 = (8192 + 128 * 64) * 4;    // 64KB

    cudaFuncSetAttribute(gemm_tc_kernel<128>,
                         cudaFuncAttributeMaxDynamicSharedMemorySize, smem1);
    cudaFuncSetAttribute(gemm_tc_kernel<64>,
                         cudaFuncAttributeMaxDynamicSharedMemorySize, smem2);

    // ---- fork a side stream: CSR build runs concurrently with gemm1 --------
    cudaStream_t s2;
    cudaStreamCreateWithFlags(&s2, cudaStreamNonBlocking);
    cudaEvent_t evFork, evJoin;
    cudaEventCreateWithFlags(&evFork, cudaEventDisableTiming);
    cudaEventCreateWithFlags(&evJoin, cudaEventDisableTiming);

    cudaEventRecord(evFork, 0);
    cudaStreamWaitEvent(s2, evFork, 0);

    // side stream: CSR build chain
    cudaMemsetAsync(deg, 0, (NN + 1) * sizeof(int), s2);
    hist_kernel<<<(EIN / 2 + TB - 1) / TB, TB, 0, s2>>>(ei, deg);
    scan_kernel<<<1, 1024, 0, s2>>>(deg, rowptr, wptr);
    scatter_kernel<<<(ETOT + TB - 1) / TB, TB, 0, s2>>>(ei, wptr, esrc);
    cudaEventRecord(evJoin, s2);

    // main stream: weight reorders + layer-1 GEMM (no CSR dependence)
    reorderW_kernel<<<(16 * 16 * 32 + TB - 1) / TB, TB>>>(W1, w1f, 128);
    reorderW_kernel<<<(16 * 8 * 32 + TB - 1) / TB, TB>>>(W2, w2f, 64);
    gemm_tc_kernel<128><<<gemm_blocks, TB, smem1>>>(x, w1f, att_src1, att_dst1,
                                                    h1, asrc1, adst1);

    // join: gather1 needs both gemm1 outputs and the CSR
    cudaStreamWaitEvent(0, evJoin, 0);
    gather1_kernel<<<node_warp_blocks, TB>>>(h1, asrc1, adst1, rowptr, esrc, b1, agg1);

    // ---- layer 2 ----
    gemm_tc_kernel<64><<<gemm_blocks, TB, smem2>>>(agg1, w2f, att_src2, att_dst2,
                                                   h2, asrc2, adst2);
    gather2_kernel<<<node_warp_blocks, TB>>>(h2, asrc2, adst2, rowptr, esrc, b2, out);
}